// round 15
// baseline (speedup 1.0000x reference)
#include <cuda_runtime.h>
#include <cuda_fp16.h>
#include <math.h>
#include <stdint.h>

#define D_MODEL 1024
#define N_HEADS 16
#define HEAD_DIM 64
#define SEQ 2048
#define MAXB 2

typedef unsigned short ushort_t;

// ---------------- scratch (no allocations allowed) ----------------
__device__ __align__(1024) float g_q[MAXB * N_HEADS * SEQ * HEAD_DIM];
__device__ __align__(1024) float g_k[MAXB * N_HEADS * SEQ * HEAD_DIM];
__device__ __align__(1024) ushort_t g_qh[MAXB * N_HEADS * SEQ * HEAD_DIM];  // fp16 hi Q
__device__ __align__(1024) ushort_t g_ql[MAXB * N_HEADS * SEQ * HEAD_DIM];  // fp16 lo Q
__device__ __align__(1024) ushort_t g_kh[MAXB * N_HEADS * SEQ * HEAD_DIM];  // fp16 K
__device__ __align__(1024) ushort_t g_vh[MAXB * N_HEADS * SEQ * HEAD_DIM];  // fp16 V
__device__ __align__(1024) ushort_t g_xh[MAXB * SEQ * D_MODEL];   // fp16 hi of x / attn-out
__device__ __align__(1024) ushort_t g_xl[MAXB * SEQ * D_MODEL];   // fp16 lo
__device__ __align__(1024) ushort_t g_wh[4 * D_MODEL * D_MODEL];  // fp16 weights (rounded)

// ---------------- helpers ----------------
__device__ __forceinline__ uint32_t stou(const void* p) {
    uint32_t a;
    asm("{ .reg .u64 t; cvta.to.shared.u64 t, %1; cvt.u32.u64 %0, t; }"
        : "=r"(a) : "l"(p));
    return a;
}
__device__ __forceinline__ uint32_t hpack(float lo, float hi) {
    uint32_t r;
    asm("cvt.rn.f16x2.f32 %0, %1, %2;" : "=r"(r) : "f"(hi), "f"(lo));
    return r;
}
__device__ __forceinline__ float hr(float x) {   // round to fp16, back to float
    return __half2float(__float2half_rn(x));
}
__device__ __forceinline__ ushort_t hu(float x) {
    __half_raw r = __float2half_rn(x);
    return r.x;
}
__device__ __forceinline__ void cpasync16(uint32_t dst, const void* src) {
    asm volatile("cp.async.cg.shared.global [%0], [%1], 16;"
                 :: "r"(dst), "l"(src) : "memory");
}
#define CP_COMMIT() asm volatile("cp.async.commit_group;" ::: "memory")
#define CP_WAIT1()  asm volatile("cp.async.wait_group 1;" ::: "memory")
#define CP_WAIT0()  asm volatile("cp.async.wait_group 0;" ::: "memory")

__device__ __forceinline__ void ldx4(uint32_t r[4], uint32_t addr) {
    asm volatile("ldmatrix.sync.aligned.m8n8.x4.shared.b16 {%0,%1,%2,%3}, [%4];"
                 : "=r"(r[0]), "=r"(r[1]), "=r"(r[2]), "=r"(r[3]) : "r"(addr));
}
__device__ __forceinline__ void ldx4t(uint32_t r[4], uint32_t addr) {
    asm volatile("ldmatrix.sync.aligned.m8n8.x4.trans.shared.b16 {%0,%1,%2,%3}, [%4];"
                 : "=r"(r[0]), "=r"(r[1]), "=r"(r[2]), "=r"(r[3]) : "r"(addr));
}
__device__ __forceinline__ void mma_f16(float c[4], const uint32_t a[4],
                                        uint32_t b0, uint32_t b1) {
    asm volatile(
        "mma.sync.aligned.m16n8k16.row.col.f32.f16.f16.f32 "
        "{%0,%1,%2,%3}, {%4,%5,%6,%7}, {%8,%9}, {%0,%1,%2,%3};"
        : "+f"(c[0]), "+f"(c[1]), "+f"(c[2]), "+f"(c[3])
        : "r"(a[0]), "r"(a[1]), "r"(a[2]), "r"(a[3]), "r"(b0), "r"(b1));
}

// ---------------- fused split kernel ----------------
// z=0: x -> fp16 hi + lo (grid-stride). z=1..4: weight -> fp16 round.
__global__ void split_all(const float* __restrict__ x,
                          const float* __restrict__ w0, const float* __restrict__ w1,
                          const float* __restrict__ w2, const float* __restrict__ w3,
                          uint2* __restrict__ xh, uint2* __restrict__ xl,
                          ushort_t* __restrict__ wh, int xn4) {
    int z = blockIdx.y;
    if (z == 0) {
        const float4* s4 = (const float4*)x;
        for (int i = blockIdx.x * 256 + threadIdx.x; i < xn4; i += gridDim.x * 256) {
            float4 v = s4[i];
            float hx = hr(v.x), hy = hr(v.y), hz = hr(v.z), hw = hr(v.w);
            uint2 h, l;
            h.x = hpack(hx, hy); h.y = hpack(hz, hw);
            l.x = hpack(v.x - hx, v.y - hy); l.y = hpack(v.z - hz, v.w - hw);
            xh[i] = h; xl[i] = l;
        }
    } else {
        int y = z - 1;
        const float* w = (y == 0) ? w0 : (y == 1) ? w1 : (y == 2) ? w2 : w3;
        const int n4 = (D_MODEL * D_MODEL) / 4;
        const float4* s4 = (const float4*)w;
        uint2* h4 = (uint2*)(wh + (size_t)y * D_MODEL * D_MODEL);
        for (int i = blockIdx.x * 256 + threadIdx.x; i < n4; i += gridDim.x * 256) {
            float4 v = s4[i];
            uint2 h;
            h.x = hpack(hr(v.x), hr(v.y));
            h.y = hpack(hr(v.z), hr(v.w));
            h4[i] = h;
        }
    }
}

// ---------------------------------------------------------------------------
// fp16 2-pass GEMM: D = (Ah+Al)*Bh^T via m16n8k16 + ldmatrix.
// Tile 128x128, BK=32, 8 warps (2x4), warp tile 64x32.
// 3-stage cp.async ring, ONE __syncthreads per chunk. 2 CTAs/SM.
// QKV=1: z=0 -> q fp32 [B,H,S,HD]; z=1 -> k fp32; z=2 -> V fp16 VH.
// QKV=0: fp32 row-major out.
// ---------------------------------------------------------------------------
#define GP 80                 // bytes per 32-half row (64 + 16 pad)
#define OPB (128 * GP)        // 10240
#define STAGEB (3 * OPB)      // Ah, Al, Bh = 30720
#define NSTG 3
#define NCH (D_MODEL / 32)    // 32

template <int QKV>
__global__ void __launch_bounds__(256, 2) tc_gemm(
    const ushort_t* __restrict__ Ah, const ushort_t* __restrict__ Al,
    const ushort_t* __restrict__ Wh,
    float* __restrict__ C0, float* __restrict__ C1,
    ushort_t* __restrict__ VH, int S) {
    extern __shared__ char smc[];
    uint32_t sb = stou(smc);

    int tid = threadIdx.x;
    int lane = tid & 31;
    int wid = tid >> 5;
    int warp_m = wid >> 2;
    int warp_n = wid & 3;

    int mBase = blockIdx.x * 128;
    int nBase = blockIdx.y * 128;

    const ushort_t* Bh = Wh;
    if (QKV) Bh = Wh + (size_t)blockIdx.z * D_MODEL * D_MODEL;

    int r = tid >> 2, sg = tid & 3;
    const ushort_t* pAh = Ah + (size_t)(mBase + r) * D_MODEL + sg * 8;
    const ushort_t* pAl = Al + (size_t)(mBase + r) * D_MODEL + sg * 8;
    const ushort_t* pBh = Bh + (size_t)(nBase + r) * D_MODEL + sg * 8;
    uint32_t dst0 = (uint32_t)(r * GP + sg * 16);
    const uint32_t rStep = 64 * GP;
    const size_t gStep = (size_t)64 * D_MODEL;

#define STAGE(buf, k0)                                                        \
    do {                                                                      \
        uint32_t s0 = sb + (uint32_t)(buf) * STAGEB + dst0;                   \
        cpasync16(s0,                   pAh + (k0));                          \
        cpasync16(s0 + rStep,           pAh + (k0) + gStep);                  \
        cpasync16(s0 + OPB,             pAl + (k0));                          \
        cpasync16(s0 + OPB + rStep,     pAl + (k0) + gStep);                  \
        cpasync16(s0 + 2 * OPB,         pBh + (k0));                          \
        cpasync16(s0 + 2 * OPB + rStep, pBh + (k0) + gStep);                  \
        CP_COMMIT();                                                          \
    } while (0)

    float c[4][4][4];
#pragma unroll
    for (int mi = 0; mi < 4; ++mi)
#pragma unroll
        for (int ni = 0; ni < 4; ++ni)
#pragma unroll
            for (int q = 0; q < 4; ++q) c[mi][ni][q] = 0.0f;

    uint32_t aOff = (uint32_t)((warp_m * 64 + (lane & 15)) * GP + (lane >> 4) * 16);
    uint32_t bOff = (uint32_t)((warp_n * 32 + (lane & 15)) * GP + (lane >> 4) * 16);

    STAGE(0, 0);
    STAGE(1, 32);

    int stgIdx = 0;      // buffer being computed
    int nxtIdx = 2;      // next buffer to fill
    for (int ch = 0; ch < NCH; ++ch) {
        if (ch + 1 < NCH) CP_WAIT1(); else CP_WAIT0();
        __syncthreads();

        uint32_t stg = sb + (uint32_t)stgIdx * STAGEB;
        if (ch + 2 < NCH) {
            STAGE(nxtIdx, (ch + 2) * 32);
        }

#pragma unroll
        for (int ks = 0; ks < 2; ++ks) {
            uint32_t ah[4][4], al[4][4], bh4[2][4];
#pragma unroll
            for (int mi = 0; mi < 4; ++mi) {
                uint32_t a = stg + aOff + (uint32_t)(mi * 16 * GP + ks * 32);
                ldx4(ah[mi], a);
                ldx4(al[mi], a + OPB);
            }
#pragma unroll
            for (int np = 0; np < 2; ++np) {
                uint32_t a = stg + 2 * OPB + bOff + (uint32_t)(np * 16 * GP + ks * 32);
                ldx4(bh4[np], a);
            }
#pragma unroll
            for (int mi = 0; mi < 4; ++mi)
#pragma unroll
                for (int np = 0; np < 2; ++np) {
                    mma_f16(c[mi][2 * np], ah[mi], bh4[np][0], bh4[np][2]);
                    mma_f16(c[mi][2 * np], al[mi], bh4[np][0], bh4[np][2]);
                    mma_f16(c[mi][2 * np + 1], ah[mi], bh4[np][1], bh4[np][3]);
                    mma_f16(c[mi][2 * np + 1], al[mi], bh4[np][1], bh4[np][3]);
                }
        }
        stgIdx = (stgIdx == NSTG - 1) ? 0 : stgIdx + 1;
        nxtIdx = (nxtIdx == NSTG - 1) ? 0 : nxtIdx + 1;
    }
#undef STAGE

    int g = lane >> 2, t = lane & 3;
#pragma unroll
    for (int mi = 0; mi < 4; ++mi) {
#pragma unroll
        for (int ni = 0; ni < 4; ++ni) {
            int r0 = mBase + warp_m * 64 + mi * 16 + g;
            int cc = nBase + warp_n * 32 + ni * 8 + 2 * t;
            float2 v0 = make_float2(c[mi][ni][0], c[mi][ni][1]);
            float2 v1 = make_float2(c[mi][ni][2], c[mi][ni][3]);
            if (!QKV) {
                *(float2*)(C0 + (size_t)r0 * D_MODEL + cc) = v0;
                *(float2*)(C0 + (size_t)(r0 + 8) * D_MODEL + cc) = v1;
            } else {
                int h = cc >> 6, hd = cc & 63;
                int b0 = r0 / S, s0 = r0 - b0 * S;
                int r1 = r0 + 8;
                int b1 = r1 / S, s1 = r1 - b1 * S;
                size_t o0 = (((size_t)b0 * N_HEADS + h) * S + s0) * HEAD_DIM + hd;
                size_t o1 = (((size_t)b1 * N_HEADS + h) * S + s1) * HEAD_DIM + hd;
                if (blockIdx.z == 2) {
                    *(uint32_t*)(VH + o0) = hpack(hr(v0.x), hr(v0.y));
                    *(uint32_t*)(VH + o1) = hpack(hr(v1.x), hr(v1.y));
                } else {
                    float* C = (blockIdx.z == 0) ? C0 : C1;
                    *(float2*)(C + o0) = v0;
                    *(float2*)(C + o1) = v1;
                }
            }
        }
    }
}

// ---------------------------------------------------------------------------
// Fused RoPE + fp16 split(Q, pre-scaled 1/8) / round(K). [BH, S, HD].
// ---------------------------------------------------------------------------
__global__ void rope_split(const float* __restrict__ q, const float* __restrict__ k,
                           ushort_t* __restrict__ qh, ushort_t* __restrict__ ql,
                           ushort_t* __restrict__ kh, int BH, int S) {
    int idx = blockIdx.x * blockDim.x + threadIdx.x;
    int total = BH * S * 32;
    if (idx >= total) return;
    int j = idx & 31;
    int s = (idx >> 5) % S;
    int bh = idx / (32 * S);

    float inv = powf(10000.0f, -(float)j / 32.0f);
    float ang = (float)s * inv;
    float sn, cs;
    sincosf(ang, &sn, &cs);

    size_t base = ((size_t)bh * S + s) * HEAD_DIM;
    float q1 = q[base + j], q2 = q[base + j + 32];
    float qa = (q1 * cs - q2 * sn) * 0.125f;
    float qb = (q2 * cs + q1 * sn) * 0.125f;
    float qah = hr(qa), qbh = hr(qb);
    qh[base + j] = hu(qa);           ql[base + j] = hu(qa - qah);
    qh[base + j + 32] = hu(qb);      ql[base + j + 32] = hu(qb - qbh);

    float k1 = k[base + j], k2 = k[base + j + 32];
    kh[base + j] = hu(k1 * cs - k2 * sn);
    kh[base + j + 32] = hu(k2 * cs + k1 * sn);
}

// ---------------------------------------------------------------------------
// Flash attention, fp16 2-pass, register-lean. 64 q/CTA, 64-key tiles,
// 4 warps; warp owns rows [16w,16w+16). Q-lo fragments reloaded per slab,
// P fragments transient (exp->pack->PV fused per 16-key slab).
// Target: <=128 regs -> 4 CTAs/SM.
// ---------------------------------------------------------------------------
#define FPB 144               // bytes per 64-half row (128 + 16 pad)
#define FT 9216               // one tile
#define FST (2 * FT)          // stage: Kh, Vh = 18432
#define FQ (2 * FST)          // Q region at 36864
#define FL_SMEM (FQ + 2 * FT) // 55296

__global__ void __launch_bounds__(128, 4) flash_f16(const ushort_t* __restrict__ QH,
                                                    const ushort_t* __restrict__ QL,
                                                    const ushort_t* __restrict__ KH,
                                                    const ushort_t* __restrict__ VH,
                                                    ushort_t* __restrict__ OH,
                                                    ushort_t* __restrict__ OL, int S) {
    extern __shared__ char smc[];
    uint32_t sb = stou(smc);

    int tid = threadIdx.x;
    int lane = tid & 31;
    int w = tid >> 5;
    int g = lane >> 2, t = lane & 3;

    int qb = (gridDim.x - 1 - blockIdx.x) * 64;   // heavy blocks first
    int bh = blockIdx.y;
    size_t hoff = (size_t)bh * S * HEAD_DIM;
    const ushort_t* qhp = QH + hoff;
    const ushort_t* qlp = QL + hoff;
    const ushort_t* khp = KH + hoff;
    const ushort_t* vhp = VH + hoff;

    int nkb = qb / 64 + 1;

    int rr = tid >> 1, sg2 = (tid & 1) * 4;
#define LOAD_TILE(dst, src)                                                   \
    do {                                                                      \
        uint32_t d_ = (dst) + (uint32_t)(rr * FPB + sg2 * 16);                \
        const ushort_t* s_ = (src) + rr * 64 + sg2 * 8;                       \
        cpasync16(d_, s_);           cpasync16(d_ + 16, s_ + 8);              \
        cpasync16(d_ + 32, s_ + 16); cpasync16(d_ + 48, s_ + 24);             \
    } while (0)

#define STAGE_KV(kb, st)                                                      \
    do {                                                                      \
        uint32_t s0_ = sb + (uint32_t)(st) * FST;                             \
        size_t off_ = (size_t)(kb) * 64 * HEAD_DIM;                           \
        LOAD_TILE(s0_,      khp + off_);                                      \
        LOAD_TILE(s0_ + FT, vhp + off_);                                      \
        CP_COMMIT();                                                          \
    } while (0)

    STAGE_KV(0, 0);
    LOAD_TILE(sb + FQ, qhp + (size_t)qb * HEAD_DIM);
    LOAD_TILE(sb + FQ + FT, qlp + (size_t)qb * HEAD_DIM);
    CP_COMMIT();
    CP_WAIT0();
    __syncthreads();

    // hoist only Q-hi fragments; Q-lo reloaded per slab (saves 16 regs)
    uint32_t qfBase = sb + FQ + (uint32_t)((w * 16 + (lane & 15)) * FPB + (lane >> 4) * 16);
    uint32_t qf_h[4][4];
#pragma unroll
    for (int ks = 0; ks < 4; ++ks) ldx4(qf_h[ks], qfBase + ks * 32);

    float cO[8][4];
#pragma unroll
    for (int nt = 0; nt < 8; ++nt)
#pragma unroll
        for (int q = 0; q < 4; ++q) cO[nt][q] = 0.0f;
    float m0 = -1e30f, m1 = -1e30f, l0 = 0.0f, l1 = 0.0f;

    for (int kb = 0; kb < nkb; ++kb) {
        int st = kb & 1;
        CP_WAIT0();
        __syncthreads();
        if (kb + 1 < nkb) STAGE_KV(kb + 1, st ^ 1);

        // ---- S = Q K^T (2-pass: (Qh+Ql)·Kh) ----
        float cS[8][4];
#pragma unroll
        for (int nt = 0; nt < 8; ++nt)
#pragma unroll
            for (int q = 0; q < 4; ++q) cS[nt][q] = 0.0f;

        uint32_t kBase = sb + (uint32_t)st * FST +
                         (uint32_t)((lane & 15) * FPB + (lane >> 4) * 16);
#pragma unroll
        for (int ks = 0; ks < 4; ++ks) {
            uint32_t qlt[4];
            ldx4(qlt, qfBase + FT + ks * 32);
#pragma unroll
            for (int np = 0; np < 4; ++np) {
                uint32_t a = kBase + (uint32_t)(np * 16 * FPB + ks * 32);
                uint32_t bh4[4];
                ldx4(bh4, a);
                mma_f16(cS[2 * np], qf_h[ks], bh4[0], bh4[2]);
                mma_f16(cS[2 * np], qlt, bh4[0], bh4[2]);
                mma_f16(cS[2 * np + 1], qf_h[ks], bh4[1], bh4[3]);
                mma_f16(cS[2 * np + 1], qlt, bh4[1], bh4[3]);
            }
        }

        // ---- causal mask (diagonal block only) ----
        if (kb == nkb - 1) {
            int rg0 = qb + w * 16 + g, rg1 = rg0 + 8;
#pragma unroll
            for (int nt = 0; nt < 8; ++nt) {
                int c0 = kb * 64 + nt * 8 + 2 * t;
                if (c0 > rg0) cS[nt][0] = -1e30f;
                if (c0 + 1 > rg0) cS[nt][1] = -1e30f;
                if (c0 > rg1) cS[nt][2] = -1e30f;
                if (c0 + 1 > rg1) cS[nt][3] = -1e30f;
            }
        }

        // ---- online softmax max/alpha ----
        float mx0 = -1e30f, mx1 = -1e30f;
#pragma unroll
        for (int nt = 0; nt < 8; ++nt) {
            mx0 = fmaxf(mx0, fmaxf(cS[nt][0], cS[nt][1]));
            mx1 = fmaxf(mx1, fmaxf(cS[nt][2], cS[nt][3]));
        }
        mx0 = fmaxf(mx0, __shfl_xor_sync(0xffffffffu, mx0, 1));
        mx0 = fmaxf(mx0, __shfl_xor_sync(0xffffffffu, mx0, 2));
        mx1 = fmaxf(mx1, __shfl_xor_sync(0xffffffffu, mx1, 1));
        mx1 = fmaxf(mx1, __shfl_xor_sync(0xffffffffu, mx1, 2));

        float mn0 = fmaxf(m0, mx0), mn1 = fmaxf(m1, mx1);
        float a0 = __expf(m0 - mn0), a1 = __expf(m1 - mn1);
        m0 = mn0; m1 = mn1;

#pragma unroll
        for (int nt = 0; nt < 8; ++nt) {
            cO[nt][0] *= a0; cO[nt][1] *= a0;
            cO[nt][2] *= a1; cO[nt][3] *= a1;
        }

        // ---- per 16-key slab: exp -> pack transient P -> PV mma ----
        uint32_t vBase = sb + (uint32_t)st * FST + FT +
                         (uint32_t)((lane & 15) * FPB + (lane >> 4) * 16);
        float s0 = 0.0f, s1 = 0.0f;
#pragma unroll
        for (int ks = 0; ks < 4; ++ks) {
            uint32_t pht[4], plt[4];
#pragma unroll
            for (int e2 = 0; e2 < 2; ++e2) {
                int nt = 2 * ks + e2;
                float p0 = __expf(cS[nt][0] - mn0);
                float p1 = __expf(cS[nt][1] - mn0);
                float p2 = __expf(cS[nt][2] - mn1);
                float p3 = __expf(cS[nt][3] - mn1);
                s0 += p0 + p1;
                s1 += p2 + p3;
                float h0 = hr(p0), h1 = hr(p1), h2 = hr(p2), h3 = hr(p3);
                pht[e2 * 2] = hpack(h0, h1);
                pht[e2 * 2 + 1] = hpack(h2, h3);
                plt[e2 * 2] = hpack(p0 - h0, p1 - h1);
                plt[e2 * 2 + 1] = hpack(p2 - h2, p3 - h3);
            }
#pragma unroll
            for (int np = 0; np < 4; ++np) {
                uint32_t a = vBase + (uint32_t)(ks * 16 * FPB + np * 32);
                uint32_t vh4[4];
                ldx4t(vh4, a);
                mma_f16(cO[2 * np], pht, vh4[0], vh4[1]);
                mma_f16(cO[2 * np], plt, vh4[0], vh4[1]);
                mma_f16(cO[2 * np + 1], pht, vh4[2], vh4[3]);
                mma_f16(cO[2 * np + 1], plt, vh4[2], vh4[3]);
            }
        }
        s0 += __shfl_xor_sync(0xffffffffu, s0, 1);
        s0 += __shfl_xor_sync(0xffffffffu, s0, 2);
        s1 += __shfl_xor_sync(0xffffffffu, s1, 1);
        s1 += __shfl_xor_sync(0xffffffffu, s1, 2);
        l0 = l0 * a0 + s0;
        l1 = l1 * a1 + s1;
    }
#undef STAGE_KV
#undef LOAD_TILE

    // ---- finalize: scale by 1/l, split to fp16 hi/lo for the Wo GEMM ----
    float li0 = 1.0f / l0, li1 = 1.0f / l1;
    int b = bh >> 4, h = bh & 15;
    int row0 = qb + w * 16 + g;
    size_t base0 = ((size_t)(b * S + row0)) * D_MODEL + h * HEAD_DIM;
    size_t base1 = base0 + (size_t)8 * D_MODEL;
#pragma unroll
    for (int nt = 0; nt < 8; ++nt) {
        int d = nt * 8 + 2 * t;
        float o00 = cO[nt][0] * li0, o01 = cO[nt][1] * li0;
        float o10 = cO[nt][2] * li1, o11 = cO[nt][3] * li1;
        float h00 = hr(o00), h01 = hr(o01), h10 = hr(o10), h11 = hr(o11);
        *(uint32_t*)(OH + base0 + d) = hpack(h00, h01);
        *(uint32_t*)(OL + base0 + d) = hpack(o00 - h00, o01 - h01);
        *(uint32_t*)(OH + base1 + d) = hpack(h10, h11);
        *(uint32_t*)(OL + base1 + d) = hpack(o10 - h10, o11 - h11);
    }
}

// ---------------- host side ----------------
extern "C" void kernel_launch(void* const* d_in, const int* in_sizes, int n_in,
                              void* d_out, int out_size) {
    const float* x  = (const float*)d_in[0];
    const float* Wq = (const float*)d_in[1];
    const float* Wk = (const float*)d_in[2];
    const float* Wv = (const float*)d_in[3];
    const float* Wo = (const float*)d_in[4];

    int B = in_sizes[0] / (SEQ * D_MODEL);
    if (B < 1) B = 1;
    if (B > MAXB) B = MAXB;
    int T = B * SEQ;
    int BH = B * N_HEADS;

    float *q, *k;
    ushort_t *qh, *ql, *kh, *vh, *xh, *xl, *wh;
    cudaGetSymbolAddress((void**)&q, g_q);
    cudaGetSymbolAddress((void**)&k, g_k);
    cudaGetSymbolAddress((void**)&qh, g_qh);
    cudaGetSymbolAddress((void**)&ql, g_ql);
    cudaGetSymbolAddress((void**)&kh, g_kh);
    cudaGetSymbolAddress((void**)&vh, g_vh);
    cudaGetSymbolAddress((void**)&xh, g_xh);
    cudaGetSymbolAddress((void**)&xl, g_xl);
    cudaGetSymbolAddress((void**)&wh, g_wh);

    const int GSMEM = NSTG * STAGEB;   // 92160
    cudaFuncSetAttribute(tc_gemm<1>, cudaFuncAttributeMaxDynamicSharedMemorySize, GSMEM);
    cudaFuncSetAttribute(tc_gemm<0>, cudaFuncAttributeMaxDynamicSharedMemorySize, GSMEM);
    cudaFuncSetAttribute(flash_f16, cudaFuncAttributeMaxDynamicSharedMemorySize, FL_SMEM);

    const size_t WSZ = (size_t)D_MODEL * D_MODEL;

    // 1) single fused split launch: x (hi/lo) + all 4 weights (round)
    int xn4 = T * D_MODEL / 4;
    split_all<<<dim3(160, 5), 256>>>(x, Wq, Wk, Wv, Wo,
                                     (uint2*)xh, (uint2*)xl, wh, xn4);

    // 2) QKV projections: q,k fp32; V written fp16
    tc_gemm<1><<<dim3(T / 128, D_MODEL / 128, 3), 256, GSMEM>>>(
        xh, xl, wh, q, k, vh, SEQ);

    // 3) fused RoPE: Q split fp16 hi/lo (scaled), K rounded fp16
    int tot = BH * SEQ * 32;
    rope_split<<<(tot + 255) / 256, 256>>>(q, k, qh, ql, kh, BH, SEQ);

    // 4) flash attention (fp16 2-pass; 4 CTAs/SM; writes split hi/lo O)
    flash_f16<<<dim3(SEQ / 64, BH), 128, FL_SMEM>>>(qh, ql, kh, vh, xh, xl, SEQ);

    // 5) output projection
    tc_gemm<0><<<dim3(T / 128, D_MODEL / 128, 1), 256, GSMEM>>>(
        xh, xl, wh + 3 * WSZ, (float*)d_out, nullptr, nullptr, SEQ);
}

// round 16
// speedup vs baseline: 1.5755x; 1.5755x over previous
#include <cuda_runtime.h>
#include <cuda_fp16.h>
#include <math.h>
#include <stdint.h>

#define D_MODEL 1024
#define N_HEADS 16
#define HEAD_DIM 64
#define SEQ 2048
#define MAXB 2

typedef unsigned short ushort_t;

// ---------------- scratch (no allocations allowed) ----------------
__device__ __align__(1024) float g_q[MAXB * N_HEADS * SEQ * HEAD_DIM];
__device__ __align__(1024) float g_k[MAXB * N_HEADS * SEQ * HEAD_DIM];
__device__ __align__(1024) ushort_t g_qh[MAXB * N_HEADS * SEQ * HEAD_DIM];  // fp16 hi Q
__device__ __align__(1024) ushort_t g_ql[MAXB * N_HEADS * SEQ * HEAD_DIM];  // fp16 lo Q
__device__ __align__(1024) ushort_t g_kh[MAXB * N_HEADS * SEQ * HEAD_DIM];  // fp16 K
__device__ __align__(1024) ushort_t g_vh[MAXB * N_HEADS * SEQ * HEAD_DIM];  // fp16 V
__device__ __align__(1024) ushort_t g_xh[MAXB * SEQ * D_MODEL];   // fp16 hi of x / attn-out
__device__ __align__(1024) ushort_t g_xl[MAXB * SEQ * D_MODEL];   // fp16 lo
__device__ __align__(1024) ushort_t g_wh[4 * D_MODEL * D_MODEL];  // fp16 weights (rounded)

// ---------------- helpers ----------------
__device__ __forceinline__ uint32_t stou(const void* p) {
    uint32_t a;
    asm("{ .reg .u64 t; cvta.to.shared.u64 t, %1; cvt.u32.u64 %0, t; }"
        : "=r"(a) : "l"(p));
    return a;
}
__device__ __forceinline__ uint32_t hpack(float lo, float hi) {
    uint32_t r;
    asm("cvt.rn.f16x2.f32 %0, %1, %2;" : "=r"(r) : "f"(hi), "f"(lo));
    return r;
}
__device__ __forceinline__ float hr(float x) {   // round to fp16, back to float
    return __half2float(__float2half_rn(x));
}
__device__ __forceinline__ ushort_t hu(float x) {
    __half_raw r = __float2half_rn(x);
    return r.x;
}
__device__ __forceinline__ void cpasync16(uint32_t dst, const void* src) {
    asm volatile("cp.async.cg.shared.global [%0], [%1], 16;"
                 :: "r"(dst), "l"(src) : "memory");
}
#define CP_COMMIT() asm volatile("cp.async.commit_group;" ::: "memory")
#define CP_WAIT1()  asm volatile("cp.async.wait_group 1;" ::: "memory")
#define CP_WAIT0()  asm volatile("cp.async.wait_group 0;" ::: "memory")

__device__ __forceinline__ void ldx4(uint32_t r[4], uint32_t addr) {
    asm volatile("ldmatrix.sync.aligned.m8n8.x4.shared.b16 {%0,%1,%2,%3}, [%4];"
                 : "=r"(r[0]), "=r"(r[1]), "=r"(r[2]), "=r"(r[3]) : "r"(addr));
}
__device__ __forceinline__ void ldx4t(uint32_t r[4], uint32_t addr) {
    asm volatile("ldmatrix.sync.aligned.m8n8.x4.trans.shared.b16 {%0,%1,%2,%3}, [%4];"
                 : "=r"(r[0]), "=r"(r[1]), "=r"(r[2]), "=r"(r[3]) : "r"(addr));
}
__device__ __forceinline__ void mma_f16(float c[4], const uint32_t a[4],
                                        uint32_t b0, uint32_t b1) {
    asm volatile(
        "mma.sync.aligned.m16n8k16.row.col.f32.f16.f16.f32 "
        "{%0,%1,%2,%3}, {%4,%5,%6,%7}, {%8,%9}, {%0,%1,%2,%3};"
        : "+f"(c[0]), "+f"(c[1]), "+f"(c[2]), "+f"(c[3])
        : "r"(a[0]), "r"(a[1]), "r"(a[2]), "r"(a[3]), "r"(b0), "r"(b1));
}

// ---------------- fused split kernel ----------------
// z=0: x -> fp16 hi + lo (grid-stride). z=1..4: weight -> fp16 round.
__global__ void split_all(const float* __restrict__ x,
                          const float* __restrict__ w0, const float* __restrict__ w1,
                          const float* __restrict__ w2, const float* __restrict__ w3,
                          uint2* __restrict__ xh, uint2* __restrict__ xl,
                          ushort_t* __restrict__ wh, int xn4) {
    int z = blockIdx.y;
    if (z == 0) {
        const float4* s4 = (const float4*)x;
        for (int i = blockIdx.x * 256 + threadIdx.x; i < xn4; i += gridDim.x * 256) {
            float4 v = s4[i];
            float hx = hr(v.x), hy = hr(v.y), hz = hr(v.z), hw = hr(v.w);
            uint2 h, l;
            h.x = hpack(hx, hy); h.y = hpack(hz, hw);
            l.x = hpack(v.x - hx, v.y - hy); l.y = hpack(v.z - hz, v.w - hw);
            xh[i] = h; xl[i] = l;
        }
    } else {
        int y = z - 1;
        const float* w = (y == 0) ? w0 : (y == 1) ? w1 : (y == 2) ? w2 : w3;
        const int n4 = (D_MODEL * D_MODEL) / 4;
        const float4* s4 = (const float4*)w;
        uint2* h4 = (uint2*)(wh + (size_t)y * D_MODEL * D_MODEL);
        for (int i = blockIdx.x * 256 + threadIdx.x; i < n4; i += gridDim.x * 256) {
            float4 v = s4[i];
            uint2 h;
            h.x = hpack(hr(v.x), hr(v.y));
            h.y = hpack(hr(v.z), hr(v.w));
            h4[i] = h;
        }
    }
}

// ---------------------------------------------------------------------------
// fp16 2-pass GEMM (R13 verbatim): D = (Ah+Al)*Bh^T via m16n8k16 + ldmatrix.
// Tile 128x128, BK=32, 8 warps (2x4), warp tile 64x32, cp.async 2-stage.
// QKV=1: z=0 -> q fp32 [B,H,S,HD]; z=1 -> k fp32; z=2 -> V fp16 VH.
// QKV=0: fp32 row-major out.
// ---------------------------------------------------------------------------
#define GP 80                 // bytes per 32-half row (64 + 16 pad)
#define OPB (128 * GP)        // 10240
#define STAGEB (3 * OPB)      // Ah, Al, Bh = 30720
#define NCH (D_MODEL / 32)    // 32

template <int QKV>
__global__ void __launch_bounds__(256, 1) tc_gemm(
    const ushort_t* __restrict__ Ah, const ushort_t* __restrict__ Al,
    const ushort_t* __restrict__ Wh,
    float* __restrict__ C0, float* __restrict__ C1,
    ushort_t* __restrict__ VH, int S) {
    extern __shared__ char smc[];
    uint32_t sb = stou(smc);

    int tid = threadIdx.x;
    int lane = tid & 31;
    int wid = tid >> 5;
    int warp_m = wid >> 2;
    int warp_n = wid & 3;

    int mBase = blockIdx.x * 128;
    int nBase = blockIdx.y * 128;

    const ushort_t* Bh = Wh;
    if (QKV) Bh = Wh + (size_t)blockIdx.z * D_MODEL * D_MODEL;

    int r = tid >> 2, sg = tid & 3;
    const ushort_t* pAh = Ah + (size_t)(mBase + r) * D_MODEL + sg * 8;
    const ushort_t* pAl = Al + (size_t)(mBase + r) * D_MODEL + sg * 8;
    const ushort_t* pBh = Bh + (size_t)(nBase + r) * D_MODEL + sg * 8;
    uint32_t dst0 = (uint32_t)(r * GP + sg * 16);
    const uint32_t rStep = 64 * GP;
    const size_t gStep = (size_t)64 * D_MODEL;

#define STAGE(buf, k0)                                                        \
    do {                                                                      \
        uint32_t s0 = sb + (uint32_t)(buf) * STAGEB + dst0;                   \
        cpasync16(s0,                   pAh + (k0));                          \
        cpasync16(s0 + rStep,           pAh + (k0) + gStep);                  \
        cpasync16(s0 + OPB,             pAl + (k0));                          \
        cpasync16(s0 + OPB + rStep,     pAl + (k0) + gStep);                  \
        cpasync16(s0 + 2 * OPB,         pBh + (k0));                          \
        cpasync16(s0 + 2 * OPB + rStep, pBh + (k0) + gStep);                  \
    } while (0)

    float c[4][4][4];
#pragma unroll
    for (int mi = 0; mi < 4; ++mi)
#pragma unroll
        for (int ni = 0; ni < 4; ++ni)
#pragma unroll
            for (int q = 0; q < 4; ++q) c[mi][ni][q] = 0.0f;

    uint32_t aOff = (uint32_t)((warp_m * 64 + (lane & 15)) * GP + (lane >> 4) * 16);
    uint32_t bOff = (uint32_t)((warp_n * 32 + (lane & 15)) * GP + (lane >> 4) * 16);

    STAGE(0, 0);
    CP_COMMIT();

    for (int ch = 0; ch < NCH; ++ch) {
        if (ch + 1 < NCH) {
            STAGE((ch + 1) & 1, (ch + 1) * 32);
            CP_COMMIT();
            CP_WAIT1();
        } else {
            CP_WAIT0();
        }
        __syncthreads();

        uint32_t stg = sb + (uint32_t)(ch & 1) * STAGEB;
#pragma unroll
        for (int ks = 0; ks < 2; ++ks) {
            uint32_t ah[4][4], al[4][4], bh4[2][4];
#pragma unroll
            for (int mi = 0; mi < 4; ++mi) {
                uint32_t a = stg + aOff + (uint32_t)(mi * 16 * GP + ks * 32);
                ldx4(ah[mi], a);
                ldx4(al[mi], a + OPB);
            }
#pragma unroll
            for (int np = 0; np < 2; ++np) {
                uint32_t a = stg + 2 * OPB + bOff + (uint32_t)(np * 16 * GP + ks * 32);
                ldx4(bh4[np], a);
            }
#pragma unroll
            for (int mi = 0; mi < 4; ++mi)
#pragma unroll
                for (int np = 0; np < 2; ++np) {
                    mma_f16(c[mi][2 * np], ah[mi], bh4[np][0], bh4[np][2]);
                    mma_f16(c[mi][2 * np], al[mi], bh4[np][0], bh4[np][2]);
                    mma_f16(c[mi][2 * np + 1], ah[mi], bh4[np][1], bh4[np][3]);
                    mma_f16(c[mi][2 * np + 1], al[mi], bh4[np][1], bh4[np][3]);
                }
        }
        __syncthreads();
    }
#undef STAGE

    int g = lane >> 2, t = lane & 3;
#pragma unroll
    for (int mi = 0; mi < 4; ++mi) {
#pragma unroll
        for (int ni = 0; ni < 4; ++ni) {
            int r0 = mBase + warp_m * 64 + mi * 16 + g;
            int cc = nBase + warp_n * 32 + ni * 8 + 2 * t;
            float2 v0 = make_float2(c[mi][ni][0], c[mi][ni][1]);
            float2 v1 = make_float2(c[mi][ni][2], c[mi][ni][3]);
            if (!QKV) {
                *(float2*)(C0 + (size_t)r0 * D_MODEL + cc) = v0;
                *(float2*)(C0 + (size_t)(r0 + 8) * D_MODEL + cc) = v1;
            } else {
                int h = cc >> 6, hd = cc & 63;
                int b0 = r0 / S, s0 = r0 - b0 * S;
                int r1 = r0 + 8;
                int b1 = r1 / S, s1 = r1 - b1 * S;
                size_t o0 = (((size_t)b0 * N_HEADS + h) * S + s0) * HEAD_DIM + hd;
                size_t o1 = (((size_t)b1 * N_HEADS + h) * S + s1) * HEAD_DIM + hd;
                if (blockIdx.z == 2) {
                    *(uint32_t*)(VH + o0) = hpack(hr(v0.x), hr(v0.y));
                    *(uint32_t*)(VH + o1) = hpack(hr(v1.x), hr(v1.y));
                } else {
                    float* C = (blockIdx.z == 0) ? C0 : C1;
                    *(float2*)(C + o0) = v0;
                    *(float2*)(C + o1) = v1;
                }
            }
        }
    }
}

// ---------------------------------------------------------------------------
// Fused RoPE + fp16 split(Q, pre-scaled 1/8) / round(K). [BH, S, HD].
// ---------------------------------------------------------------------------
__global__ void rope_split(const float* __restrict__ q, const float* __restrict__ k,
                           ushort_t* __restrict__ qh, ushort_t* __restrict__ ql,
                           ushort_t* __restrict__ kh, int BH, int S) {
    int idx = blockIdx.x * blockDim.x + threadIdx.x;
    int total = BH * S * 32;
    if (idx >= total) return;
    int j = idx & 31;
    int s = (idx >> 5) % S;
    int bh = idx / (32 * S);

    float inv = powf(10000.0f, -(float)j / 32.0f);
    float ang = (float)s * inv;
    float sn, cs;
    sincosf(ang, &sn, &cs);

    size_t base = ((size_t)bh * S + s) * HEAD_DIM;
    float q1 = q[base + j], q2 = q[base + j + 32];
    float qa = (q1 * cs - q2 * sn) * 0.125f;
    float qb = (q2 * cs + q1 * sn) * 0.125f;
    float qah = hr(qa), qbh = hr(qb);
    qh[base + j] = hu(qa);           ql[base + j] = hu(qa - qah);
    qh[base + j + 32] = hu(qb);      ql[base + j + 32] = hu(qb - qbh);

    float k1 = k[base + j], k2 = k[base + j + 32];
    kh[base + j] = hu(k1 * cs - k2 * sn);
    kh[base + j + 32] = hu(k2 * cs + k1 * sn);
}

// ---------------------------------------------------------------------------
// Flash attention (R14 structure): fp16 2-pass QK, single-pass PV with l
// computed from the SAME fp16-rounded P used in PV (consistent ratio ->
// quantization largely cancels in O/l). 64 q/CTA, 64-key tiles, 4 warps;
// warp owns rows [16w,16w+16); hoisted Q hi+lo fragments; 3 CTAs/SM;
// heavy (late-qb) blocks first.
// ---------------------------------------------------------------------------
#define FPB 144               // bytes per 64-half row (128 + 16 pad)
#define FT 9216               // one tile
#define FST (2 * FT)          // stage: Kh, Vh = 18432
#define FQ (2 * FST)          // Q region at 36864
#define FL_SMEM (FQ + 2 * FT) // 55296

__global__ void __launch_bounds__(128, 3) flash_f16(const ushort_t* __restrict__ QH,
                                                    const ushort_t* __restrict__ QL,
                                                    const ushort_t* __restrict__ KH,
                                                    const ushort_t* __restrict__ VH,
                                                    ushort_t* __restrict__ OH,
                                                    ushort_t* __restrict__ OL, int S) {
    extern __shared__ char smc[];
    uint32_t sb = stou(smc);

    int tid = threadIdx.x;
    int lane = tid & 31;
    int w = tid >> 5;
    int g = lane >> 2, t = lane & 3;

    int qb = (gridDim.x - 1 - blockIdx.x) * 64;   // heavy blocks first
    int bh = blockIdx.y;
    size_t hoff = (size_t)bh * S * HEAD_DIM;
    const ushort_t* qhp = QH + hoff;
    const ushort_t* qlp = QL + hoff;
    const ushort_t* khp = KH + hoff;
    const ushort_t* vhp = VH + hoff;

    int nkb = qb / 64 + 1;

    int rr = tid >> 1, sg2 = (tid & 1) * 4;
#define LOAD_TILE(dst, src)                                                   \
    do {                                                                      \
        uint32_t d_ = (dst) + (uint32_t)(rr * FPB + sg2 * 16);                \
        const ushort_t* s_ = (src) + rr * 64 + sg2 * 8;                       \
        cpasync16(d_, s_);           cpasync16(d_ + 16, s_ + 8);              \
        cpasync16(d_ + 32, s_ + 16); cpasync16(d_ + 48, s_ + 24);             \
    } while (0)

#define STAGE_KV(kb, st)                                                      \
    do {                                                                      \
        uint32_t s0_ = sb + (uint32_t)(st) * FST;                             \
        size_t off_ = (size_t)(kb) * 64 * HEAD_DIM;                           \
        LOAD_TILE(s0_,      khp + off_);                                      \
        LOAD_TILE(s0_ + FT, vhp + off_);                                      \
        CP_COMMIT();                                                          \
    } while (0)

    STAGE_KV(0, 0);
    LOAD_TILE(sb + FQ, qhp + (size_t)qb * HEAD_DIM);
    LOAD_TILE(sb + FQ + FT, qlp + (size_t)qb * HEAD_DIM);
    CP_COMMIT();
    CP_WAIT0();
    __syncthreads();

    // hoist Q fragments (rows w*16..w*16+15, all 64 d)
    uint32_t qf_h[4][4], qf_l[4][4];
    {
        uint32_t a0 = sb + FQ + (uint32_t)((w * 16 + (lane & 15)) * FPB + (lane >> 4) * 16);
#pragma unroll
        for (int ks = 0; ks < 4; ++ks) {
            ldx4(qf_h[ks], a0 + ks * 32);
            ldx4(qf_l[ks], a0 + ks * 32 + FT);
        }
    }

    float cO[8][4];
#pragma unroll
    for (int nt = 0; nt < 8; ++nt)
#pragma unroll
        for (int q = 0; q < 4; ++q) cO[nt][q] = 0.0f;
    float m0 = -1e30f, m1 = -1e30f, l0 = 0.0f, l1 = 0.0f;

    for (int kb = 0; kb < nkb; ++kb) {
        int st = kb & 1;
        CP_WAIT0();
        __syncthreads();
        if (kb + 1 < nkb) STAGE_KV(kb + 1, st ^ 1);

        // ---- S = Q K^T (2-pass: (Qh+Ql)·Kh) ----
        float cS[8][4];
#pragma unroll
        for (int nt = 0; nt < 8; ++nt)
#pragma unroll
            for (int q = 0; q < 4; ++q) cS[nt][q] = 0.0f;

        uint32_t kBase = sb + (uint32_t)st * FST +
                         (uint32_t)((lane & 15) * FPB + (lane >> 4) * 16);
#pragma unroll
        for (int ks = 0; ks < 4; ++ks) {
#pragma unroll
            for (int np = 0; np < 4; ++np) {
                uint32_t a = kBase + (uint32_t)(np * 16 * FPB + ks * 32);
                uint32_t bh4[4];
                ldx4(bh4, a);
                mma_f16(cS[2 * np], qf_h[ks], bh4[0], bh4[2]);
                mma_f16(cS[2 * np], qf_l[ks], bh4[0], bh4[2]);
                mma_f16(cS[2 * np + 1], qf_h[ks], bh4[1], bh4[3]);
                mma_f16(cS[2 * np + 1], qf_l[ks], bh4[1], bh4[3]);
            }
        }

        // ---- causal mask (diagonal block only) ----
        if (kb == nkb - 1) {
            int rg0 = qb + w * 16 + g, rg1 = rg0 + 8;
#pragma unroll
            for (int nt = 0; nt < 8; ++nt) {
                int c0 = kb * 64 + nt * 8 + 2 * t;
                if (c0 > rg0) cS[nt][0] = -1e30f;
                if (c0 + 1 > rg0) cS[nt][1] = -1e30f;
                if (c0 > rg1) cS[nt][2] = -1e30f;
                if (c0 + 1 > rg1) cS[nt][3] = -1e30f;
            }
        }

        // ---- online softmax; P rounded to fp16, l accumulated from the
        //      SAME rounded values (consistent normalization) ----
        float mx0 = -1e30f, mx1 = -1e30f;
#pragma unroll
        for (int nt = 0; nt < 8; ++nt) {
            mx0 = fmaxf(mx0, fmaxf(cS[nt][0], cS[nt][1]));
            mx1 = fmaxf(mx1, fmaxf(cS[nt][2], cS[nt][3]));
        }
        mx0 = fmaxf(mx0, __shfl_xor_sync(0xffffffffu, mx0, 1));
        mx0 = fmaxf(mx0, __shfl_xor_sync(0xffffffffu, mx0, 2));
        mx1 = fmaxf(mx1, __shfl_xor_sync(0xffffffffu, mx1, 1));
        mx1 = fmaxf(mx1, __shfl_xor_sync(0xffffffffu, mx1, 2));

        float mn0 = fmaxf(m0, mx0), mn1 = fmaxf(m1, mx1);
        float a0 = __expf(m0 - mn0), a1 = __expf(m1 - mn1);
        m0 = mn0; m1 = mn1;

        uint32_t ph[4][4];
        float s0 = 0.0f, s1 = 0.0f;
#pragma unroll
        for (int nt = 0; nt < 8; ++nt) {
            float p0 = __expf(cS[nt][0] - mn0);
            float p1 = __expf(cS[nt][1] - mn0);
            float p2 = __expf(cS[nt][2] - mn1);
            float p3 = __expf(cS[nt][3] - mn1);
            float h0 = hr(p0), h1 = hr(p1), h2 = hr(p2), h3 = hr(p3);
            s0 += h0 + h1;
            s1 += h2 + h3;
            int ks = nt >> 1;
            int o = (nt & 1) * 2;
            ph[ks][o] = hpack(h0, h1);
            ph[ks][o + 1] = hpack(h2, h3);
        }
        s0 += __shfl_xor_sync(0xffffffffu, s0, 1);
        s0 += __shfl_xor_sync(0xffffffffu, s0, 2);
        s1 += __shfl_xor_sync(0xffffffffu, s1, 1);
        s1 += __shfl_xor_sync(0xffffffffu, s1, 2);
        l0 = l0 * a0 + s0;
        l1 = l1 * a1 + s1;

        // ---- O = O*alpha + Ph·Vh (single pass) ----
#pragma unroll
        for (int nt = 0; nt < 8; ++nt) {
            cO[nt][0] *= a0; cO[nt][1] *= a0;
            cO[nt][2] *= a1; cO[nt][3] *= a1;
        }
        uint32_t vBase = sb + (uint32_t)st * FST + FT +
                         (uint32_t)((lane & 15) * FPB + (lane >> 4) * 16);
#pragma unroll
        for (int ks = 0; ks < 4; ++ks) {
#pragma unroll
            for (int np = 0; np < 4; ++np) {
                uint32_t a = vBase + (uint32_t)(ks * 16 * FPB + np * 32);
                uint32_t vh4[4];
                ldx4t(vh4, a);
                mma_f16(cO[2 * np], ph[ks], vh4[0], vh4[1]);
                mma_f16(cO[2 * np + 1], ph[ks], vh4[2], vh4[3]);
            }
        }
    }
#undef STAGE_KV
#undef LOAD_TILE

    // ---- finalize: scale by 1/l, split to fp16 hi/lo for the Wo GEMM ----
    float li0 = 1.0f / l0, li1 = 1.0f / l1;
    int b = bh >> 4, h = bh & 15;
    int row0 = qb + w * 16 + g;
    size_t base0 = ((size_t)(b * S + row0)) * D_MODEL + h * HEAD_DIM;
    size_t base1 = base0 + (size_t)8 * D_MODEL;
#pragma unroll
    for (int nt = 0; nt < 8; ++nt) {
        int d = nt * 8 + 2 * t;
        float o00 = cO[nt][0] * li0, o01 = cO[nt][1] * li0;
        float o10 = cO[nt][2] * li1, o11 = cO[nt][3] * li1;
        float h00 = hr(o00), h01 = hr(o01), h10 = hr(o10), h11 = hr(o11);
        *(uint32_t*)(OH + base0 + d) = hpack(h00, h01);
        *(uint32_t*)(OL + base0 + d) = hpack(o00 - h00, o01 - h01);
        *(uint32_t*)(OH + base1 + d) = hpack(h10, h11);
        *(uint32_t*)(OL + base1 + d) = hpack(o10 - h10, o11 - h11);
    }
}

// ---------------- host side ----------------
extern "C" void kernel_launch(void* const* d_in, const int* in_sizes, int n_in,
                              void* d_out, int out_size) {
    const float* x  = (const float*)d_in[0];
    const float* Wq = (const float*)d_in[1];
    const float* Wk = (const float*)d_in[2];
    const float* Wv = (const float*)d_in[3];
    const float* Wo = (const float*)d_in[4];

    int B = in_sizes[0] / (SEQ * D_MODEL);
    if (B < 1) B = 1;
    if (B > MAXB) B = MAXB;
    int T = B * SEQ;
    int BH = B * N_HEADS;

    float *q, *k;
    ushort_t *qh, *ql, *kh, *vh, *xh, *xl, *wh;
    cudaGetSymbolAddress((void**)&q, g_q);
    cudaGetSymbolAddress((void**)&k, g_k);
    cudaGetSymbolAddress((void**)&qh, g_qh);
    cudaGetSymbolAddress((void**)&ql, g_ql);
    cudaGetSymbolAddress((void**)&kh, g_kh);
    cudaGetSymbolAddress((void**)&vh, g_vh);
    cudaGetSymbolAddress((void**)&xh, g_xh);
    cudaGetSymbolAddress((void**)&xl, g_xl);
    cudaGetSymbolAddress((void**)&wh, g_wh);

    const int GSMEM = 2 * STAGEB;   // 61440
    cudaFuncSetAttribute(tc_gemm<1>, cudaFuncAttributeMaxDynamicSharedMemorySize, GSMEM);
    cudaFuncSetAttribute(tc_gemm<0>, cudaFuncAttributeMaxDynamicSharedMemorySize, GSMEM);
    cudaFuncSetAttribute(flash_f16, cudaFuncAttributeMaxDynamicSharedMemorySize, FL_SMEM);

    const size_t WSZ = (size_t)D_MODEL * D_MODEL;

    // 1) single fused split launch: x (hi/lo) + all 4 weights (round)
    int xn4 = T * D_MODEL / 4;
    split_all<<<dim3(160, 5), 256>>>(x, Wq, Wk, Wv, Wo,
                                     (uint2*)xh, (uint2*)xl, wh, xn4);

    // 2) QKV projections: q,k fp32; V written fp16
    tc_gemm<1><<<dim3(T / 128, D_MODEL / 128, 3), 256, GSMEM>>>(
        xh, xl, wh, q, k, vh, SEQ);

    // 3) fused RoPE: Q split fp16 hi/lo (scaled), K rounded fp16
    int tot = BH * SEQ * 32;
    rope_split<<<(tot + 255) / 256, 256>>>(q, k, qh, ql, kh, BH, SEQ);

    // 4) flash attention (fp16; single-pass PV; writes split hi/lo O)
    flash_f16<<<dim3(SEQ / 64, BH), 128, FL_SMEM>>>(qh, ql, kh, vh, xh, xl, SEQ);

    // 5) output projection
    tc_gemm<0><<<dim3(T / 128, D_MODEL / 128, 1), 256, GSMEM>>>(
        xh, xl, wh + 3 * WSZ, (float*)d_out, nullptr, nullptr, SEQ);
}

// round 17
// speedup vs baseline: 2.1888x; 1.3893x over previous
#include <cuda_runtime.h>
#include <cuda_fp16.h>
#include <math.h>
#include <stdint.h>

#define D_MODEL 1024
#define N_HEADS 16
#define HEAD_DIM 64
#define SEQ 2048
#define MAXB 2

typedef unsigned short ushort_t;

// ---------------- scratch (no allocations allowed) ----------------
__device__ __align__(1024) float g_q[MAXB * N_HEADS * SEQ * HEAD_DIM];
__device__ __align__(1024) float g_k[MAXB * N_HEADS * SEQ * HEAD_DIM];
__device__ __align__(1024) ushort_t g_qh[MAXB * N_HEADS * SEQ * HEAD_DIM];  // fp16 hi Q
__device__ __align__(1024) ushort_t g_ql[MAXB * N_HEADS * SEQ * HEAD_DIM];  // fp16 lo Q
__device__ __align__(1024) ushort_t g_kh[MAXB * N_HEADS * SEQ * HEAD_DIM];  // fp16 K
__device__ __align__(1024) ushort_t g_vh[MAXB * N_HEADS * SEQ * HEAD_DIM];  // fp16 V
__device__ __align__(1024) ushort_t g_xh[MAXB * SEQ * D_MODEL];   // fp16 x / attn-out (rounded)
__device__ __align__(1024) ushort_t g_wh[4 * D_MODEL * D_MODEL];  // fp16 weights (rounded)

// ---------------- helpers ----------------
__device__ __forceinline__ uint32_t stou(const void* p) {
    uint32_t a;
    asm("{ .reg .u64 t; cvta.to.shared.u64 t, %1; cvt.u32.u64 %0, t; }"
        : "=r"(a) : "l"(p));
    return a;
}
__device__ __forceinline__ uint32_t hpack(float lo, float hi) {
    uint32_t r;
    asm("cvt.rn.f16x2.f32 %0, %1, %2;" : "=r"(r) : "f"(hi), "f"(lo));
    return r;
}
__device__ __forceinline__ float hr(float x) {   // round to fp16, back to float
    return __half2float(__float2half_rn(x));
}
__device__ __forceinline__ ushort_t hu(float x) {
    __half_raw r = __float2half_rn(x);
    return r.x;
}
__device__ __forceinline__ void cpasync16(uint32_t dst, const void* src) {
    asm volatile("cp.async.cg.shared.global [%0], [%1], 16;"
                 :: "r"(dst), "l"(src) : "memory");
}
#define CP_COMMIT() asm volatile("cp.async.commit_group;" ::: "memory")
#define CP_WAIT1()  asm volatile("cp.async.wait_group 1;" ::: "memory")
#define CP_WAIT0()  asm volatile("cp.async.wait_group 0;" ::: "memory")

__device__ __forceinline__ void ldx4(uint32_t r[4], uint32_t addr) {
    asm volatile("ldmatrix.sync.aligned.m8n8.x4.shared.b16 {%0,%1,%2,%3}, [%4];"
                 : "=r"(r[0]), "=r"(r[1]), "=r"(r[2]), "=r"(r[3]) : "r"(addr));
}
__device__ __forceinline__ void ldx4t(uint32_t r[4], uint32_t addr) {
    asm volatile("ldmatrix.sync.aligned.m8n8.x4.trans.shared.b16 {%0,%1,%2,%3}, [%4];"
                 : "=r"(r[0]), "=r"(r[1]), "=r"(r[2]), "=r"(r[3]) : "r"(addr));
}
__device__ __forceinline__ void mma_f16(float c[4], const uint32_t a[4],
                                        uint32_t b0, uint32_t b1) {
    asm volatile(
        "mma.sync.aligned.m16n8k16.row.col.f32.f16.f16.f32 "
        "{%0,%1,%2,%3}, {%4,%5,%6,%7}, {%8,%9}, {%0,%1,%2,%3};"
        : "+f"(c[0]), "+f"(c[1]), "+f"(c[2]), "+f"(c[3])
        : "r"(a[0]), "r"(a[1]), "r"(a[2]), "r"(a[3]), "r"(b0), "r"(b1));
}

// ---------------- fused split kernel ----------------
// z=0: x -> fp16 round (grid-stride). z=1..4: weight -> fp16 round.
__global__ void split_all(const float* __restrict__ x,
                          const float* __restrict__ w0, const float* __restrict__ w1,
                          const float* __restrict__ w2, const float* __restrict__ w3,
                          uint2* __restrict__ xh, ushort_t* __restrict__ wh, int xn4) {
    int z = blockIdx.y;
    if (z == 0) {
        const float4* s4 = (const float4*)x;
        for (int i = blockIdx.x * 256 + threadIdx.x; i < xn4; i += gridDim.x * 256) {
            float4 v = s4[i];
            uint2 h;
            h.x = hpack(hr(v.x), hr(v.y));
            h.y = hpack(hr(v.z), hr(v.w));
            xh[i] = h;
        }
    } else {
        int y = z - 1;
        const float* w = (y == 0) ? w0 : (y == 1) ? w1 : (y == 2) ? w2 : w3;
        const int n4 = (D_MODEL * D_MODEL) / 4;
        const float4* s4 = (const float4*)w;
        uint2* h4 = (uint2*)(wh + (size_t)y * D_MODEL * D_MODEL);
        for (int i = blockIdx.x * 256 + threadIdx.x; i < n4; i += gridDim.x * 256) {
            float4 v = s4[i];
            uint2 h;
            h.x = hpack(hr(v.x), hr(v.y));
            h.y = hpack(hr(v.z), hr(v.w));
            h4[i] = h;
        }
    }
}

// ---------------------------------------------------------------------------
// fp16 1-pass GEMM: D = Ah*Bh^T via m16n8k16 + ldmatrix.
// Tile 128x128, BK=32, 8 warps (2x4), warp tile 64x32, cp.async 2-stage.
// QKV=1: z=0 -> q fp32 [B,H,S,HD]; z=1 -> k fp32; z=2 -> V fp16 VH.
// QKV=0: fp32 row-major out.
// ---------------------------------------------------------------------------
#define GP 80                 // bytes per 32-half row (64 + 16 pad)
#define OPB (128 * GP)        // 10240
#define STAGEB (2 * OPB)      // Ah, Bh = 20480
#define NCH (D_MODEL / 32)    // 32

template <int QKV>
__global__ void __launch_bounds__(256, 1) tc_gemm(
    const ushort_t* __restrict__ Ah, const ushort_t* __restrict__ Wh,
    float* __restrict__ C0, float* __restrict__ C1,
    ushort_t* __restrict__ VH, int S) {
    extern __shared__ char smc[];
    uint32_t sb = stou(smc);

    int tid = threadIdx.x;
    int lane = tid & 31;
    int wid = tid >> 5;
    int warp_m = wid >> 2;
    int warp_n = wid & 3;

    int mBase = blockIdx.x * 128;
    int nBase = blockIdx.y * 128;

    const ushort_t* Bh = Wh;
    if (QKV) Bh = Wh + (size_t)blockIdx.z * D_MODEL * D_MODEL;

    int r = tid >> 2, sg = tid & 3;
    const ushort_t* pAh = Ah + (size_t)(mBase + r) * D_MODEL + sg * 8;
    const ushort_t* pBh = Bh + (size_t)(nBase + r) * D_MODEL + sg * 8;
    uint32_t dst0 = (uint32_t)(r * GP + sg * 16);
    const uint32_t rStep = 64 * GP;
    const size_t gStep = (size_t)64 * D_MODEL;

#define STAGE(buf, k0)                                                        \
    do {                                                                      \
        uint32_t s0 = sb + (uint32_t)(buf) * STAGEB + dst0;                   \
        cpasync16(s0,               pAh + (k0));                              \
        cpasync16(s0 + rStep,       pAh + (k0) + gStep);                      \
        cpasync16(s0 + OPB,         pBh + (k0));                              \
        cpasync16(s0 + OPB + rStep, pBh + (k0) + gStep);                      \
    } while (0)

    float c[4][4][4];
#pragma unroll
    for (int mi = 0; mi < 4; ++mi)
#pragma unroll
        for (int ni = 0; ni < 4; ++ni)
#pragma unroll
            for (int q = 0; q < 4; ++q) c[mi][ni][q] = 0.0f;

    uint32_t aOff = (uint32_t)((warp_m * 64 + (lane & 15)) * GP + (lane >> 4) * 16);
    uint32_t bOff = (uint32_t)((warp_n * 32 + (lane & 15)) * GP + (lane >> 4) * 16);

    STAGE(0, 0);
    CP_COMMIT();

    for (int ch = 0; ch < NCH; ++ch) {
        if (ch + 1 < NCH) {
            STAGE((ch + 1) & 1, (ch + 1) * 32);
            CP_COMMIT();
            CP_WAIT1();
        } else {
            CP_WAIT0();
        }
        __syncthreads();

        uint32_t stg = sb + (uint32_t)(ch & 1) * STAGEB;
#pragma unroll
        for (int ks = 0; ks < 2; ++ks) {
            uint32_t ah[4][4], bh4[2][4];
#pragma unroll
            for (int mi = 0; mi < 4; ++mi) {
                uint32_t a = stg + aOff + (uint32_t)(mi * 16 * GP + ks * 32);
                ldx4(ah[mi], a);
            }
#pragma unroll
            for (int np = 0; np < 2; ++np) {
                uint32_t a = stg + OPB + bOff + (uint32_t)(np * 16 * GP + ks * 32);
                ldx4(bh4[np], a);
            }
#pragma unroll
            for (int mi = 0; mi < 4; ++mi)
#pragma unroll
                for (int np = 0; np < 2; ++np) {
                    mma_f16(c[mi][2 * np], ah[mi], bh4[np][0], bh4[np][2]);
                    mma_f16(c[mi][2 * np + 1], ah[mi], bh4[np][1], bh4[np][3]);
                }
        }
        __syncthreads();
    }
#undef STAGE

    int g = lane >> 2, t = lane & 3;
#pragma unroll
    for (int mi = 0; mi < 4; ++mi) {
#pragma unroll
        for (int ni = 0; ni < 4; ++ni) {
            int r0 = mBase + warp_m * 64 + mi * 16 + g;
            int cc = nBase + warp_n * 32 + ni * 8 + 2 * t;
            float2 v0 = make_float2(c[mi][ni][0], c[mi][ni][1]);
            float2 v1 = make_float2(c[mi][ni][2], c[mi][ni][3]);
            if (!QKV) {
                *(float2*)(C0 + (size_t)r0 * D_MODEL + cc) = v0;
                *(float2*)(C0 + (size_t)(r0 + 8) * D_MODEL + cc) = v1;
            } else {
                int h = cc >> 6, hd = cc & 63;
                int b0 = r0 / S, s0 = r0 - b0 * S;
                int r1 = r0 + 8;
                int b1 = r1 / S, s1 = r1 - b1 * S;
                size_t o0 = (((size_t)b0 * N_HEADS + h) * S + s0) * HEAD_DIM + hd;
                size_t o1 = (((size_t)b1 * N_HEADS + h) * S + s1) * HEAD_DIM + hd;
                if (blockIdx.z == 2) {
                    *(uint32_t*)(VH + o0) = hpack(hr(v0.x), hr(v0.y));
                    *(uint32_t*)(VH + o1) = hpack(hr(v1.x), hr(v1.y));
                } else {
                    float* C = (blockIdx.z == 0) ? C0 : C1;
                    *(float2*)(C + o0) = v0;
                    *(float2*)(C + o1) = v1;
                }
            }
        }
    }
}

// ---------------------------------------------------------------------------
// Fused RoPE + fp16 split(Q, pre-scaled 1/8) / round(K). [BH, S, HD].
// ---------------------------------------------------------------------------
__global__ void rope_split(const float* __restrict__ q, const float* __restrict__ k,
                           ushort_t* __restrict__ qh, ushort_t* __restrict__ ql,
                           ushort_t* __restrict__ kh, int BH, int S) {
    int idx = blockIdx.x * blockDim.x + threadIdx.x;
    int total = BH * S * 32;
    if (idx >= total) return;
    int j = idx & 31;
    int s = (idx >> 5) % S;
    int bh = idx / (32 * S);

    float inv = powf(10000.0f, -(float)j / 32.0f);
    float ang = (float)s * inv;
    float sn, cs;
    sincosf(ang, &sn, &cs);

    size_t base = ((size_t)bh * S + s) * HEAD_DIM;
    float q1 = q[base + j], q2 = q[base + j + 32];
    float qa = (q1 * cs - q2 * sn) * 0.125f;
    float qb = (q2 * cs + q1 * sn) * 0.125f;
    float qah = hr(qa), qbh = hr(qb);
    qh[base + j] = hu(qa);           ql[base + j] = hu(qa - qah);
    qh[base + j + 32] = hu(qb);      ql[base + j + 32] = hu(qb - qbh);

    float k1 = k[base + j], k2 = k[base + j + 32];
    kh[base + j] = hu(k1 * cs - k2 * sn);
    kh[base + j + 32] = hu(k2 * cs + k1 * sn);
}

// ---------------------------------------------------------------------------
// Flash attention (R16 structure, unchanged): fp16 2-pass QK, single-pass PV
// with l from the SAME fp16-rounded P. 64 q/CTA, 64-key tiles, 4 warps;
// warp owns rows [16w,16w+16); hoisted Q hi+lo fragments; 3 CTAs/SM;
// heavy (late-qb) blocks first. Epilogue writes ROUNDED fp16 O only.
// ---------------------------------------------------------------------------
#define FPB 144               // bytes per 64-half row (128 + 16 pad)
#define FT 9216               // one tile
#define FST (2 * FT)          // stage: Kh, Vh = 18432
#define FQ (2 * FST)          // Q region at 36864
#define FL_SMEM (FQ + 2 * FT) // 55296

__global__ void __launch_bounds__(128, 3) flash_f16(const ushort_t* __restrict__ QH,
                                                    const ushort_t* __restrict__ QL,
                                                    const ushort_t* __restrict__ KH,
                                                    const ushort_t* __restrict__ VH,
                                                    ushort_t* __restrict__ OH, int S) {
    extern __shared__ char smc[];
    uint32_t sb = stou(smc);

    int tid = threadIdx.x;
    int lane = tid & 31;
    int w = tid >> 5;
    int g = lane >> 2, t = lane & 3;

    int qb = (gridDim.x - 1 - blockIdx.x) * 64;   // heavy blocks first
    int bh = blockIdx.y;
    size_t hoff = (size_t)bh * S * HEAD_DIM;
    const ushort_t* qhp = QH + hoff;
    const ushort_t* qlp = QL + hoff;
    const ushort_t* khp = KH + hoff;
    const ushort_t* vhp = VH + hoff;

    int nkb = qb / 64 + 1;

    int rr = tid >> 1, sg2 = (tid & 1) * 4;
#define LOAD_TILE(dst, src)                                                   \
    do {                                                                      \
        uint32_t d_ = (dst) + (uint32_t)(rr * FPB + sg2 * 16);                \
        const ushort_t* s_ = (src) + rr * 64 + sg2 * 8;                       \
        cpasync16(d_, s_);           cpasync16(d_ + 16, s_ + 8);              \
        cpasync16(d_ + 32, s_ + 16); cpasync16(d_ + 48, s_ + 24);             \
    } while (0)

#define STAGE_KV(kb, st)                                                      \
    do {                                                                      \
        uint32_t s0_ = sb + (uint32_t)(st) * FST;                             \
        size_t off_ = (size_t)(kb) * 64 * HEAD_DIM;                           \
        LOAD_TILE(s0_,      khp + off_);                                      \
        LOAD_TILE(s0_ + FT, vhp + off_);                                      \
        CP_COMMIT();                                                          \
    } while (0)

    STAGE_KV(0, 0);
    LOAD_TILE(sb + FQ, qhp + (size_t)qb * HEAD_DIM);
    LOAD_TILE(sb + FQ + FT, qlp + (size_t)qb * HEAD_DIM);
    CP_COMMIT();
    CP_WAIT0();
    __syncthreads();

    // hoist Q fragments (rows w*16..w*16+15, all 64 d)
    uint32_t qf_h[4][4], qf_l[4][4];
    {
        uint32_t a0 = sb + FQ + (uint32_t)((w * 16 + (lane & 15)) * FPB + (lane >> 4) * 16);
#pragma unroll
        for (int ks = 0; ks < 4; ++ks) {
            ldx4(qf_h[ks], a0 + ks * 32);
            ldx4(qf_l[ks], a0 + ks * 32 + FT);
        }
    }

    float cO[8][4];
#pragma unroll
    for (int nt = 0; nt < 8; ++nt)
#pragma unroll
        for (int q = 0; q < 4; ++q) cO[nt][q] = 0.0f;
    float m0 = -1e30f, m1 = -1e30f, l0 = 0.0f, l1 = 0.0f;

    for (int kb = 0; kb < nkb; ++kb) {
        int st = kb & 1;
        CP_WAIT0();
        __syncthreads();
        if (kb + 1 < nkb) STAGE_KV(kb + 1, st ^ 1);

        // ---- S = Q K^T (2-pass: (Qh+Ql)·Kh) ----
        float cS[8][4];
#pragma unroll
        for (int nt = 0; nt < 8; ++nt)
#pragma unroll
            for (int q = 0; q < 4; ++q) cS[nt][q] = 0.0f;

        uint32_t kBase = sb + (uint32_t)st * FST +
                         (uint32_t)((lane & 15) * FPB + (lane >> 4) * 16);
#pragma unroll
        for (int ks = 0; ks < 4; ++ks) {
#pragma unroll
            for (int np = 0; np < 4; ++np) {
                uint32_t a = kBase + (uint32_t)(np * 16 * FPB + ks * 32);
                uint32_t bh4[4];
                ldx4(bh4, a);
                mma_f16(cS[2 * np], qf_h[ks], bh4[0], bh4[2]);
                mma_f16(cS[2 * np], qf_l[ks], bh4[0], bh4[2]);
                mma_f16(cS[2 * np + 1], qf_h[ks], bh4[1], bh4[3]);
                mma_f16(cS[2 * np + 1], qf_l[ks], bh4[1], bh4[3]);
            }
        }

        // ---- causal mask (diagonal block only) ----
        if (kb == nkb - 1) {
            int rg0 = qb + w * 16 + g, rg1 = rg0 + 8;
#pragma unroll
            for (int nt = 0; nt < 8; ++nt) {
                int c0 = kb * 64 + nt * 8 + 2 * t;
                if (c0 > rg0) cS[nt][0] = -1e30f;
                if (c0 + 1 > rg0) cS[nt][1] = -1e30f;
                if (c0 > rg1) cS[nt][2] = -1e30f;
                if (c0 + 1 > rg1) cS[nt][3] = -1e30f;
            }
        }

        // ---- online softmax; P rounded to fp16, l from the SAME rounded P ----
        float mx0 = -1e30f, mx1 = -1e30f;
#pragma unroll
        for (int nt = 0; nt < 8; ++nt) {
            mx0 = fmaxf(mx0, fmaxf(cS[nt][0], cS[nt][1]));
            mx1 = fmaxf(mx1, fmaxf(cS[nt][2], cS[nt][3]));
        }
        mx0 = fmaxf(mx0, __shfl_xor_sync(0xffffffffu, mx0, 1));
        mx0 = fmaxf(mx0, __shfl_xor_sync(0xffffffffu, mx0, 2));
        mx1 = fmaxf(mx1, __shfl_xor_sync(0xffffffffu, mx1, 1));
        mx1 = fmaxf(mx1, __shfl_xor_sync(0xffffffffu, mx1, 2));

        float mn0 = fmaxf(m0, mx0), mn1 = fmaxf(m1, mx1);
        float a0 = __expf(m0 - mn0), a1 = __expf(m1 - mn1);
        m0 = mn0; m1 = mn1;

        uint32_t ph[4][4];
        float s0 = 0.0f, s1 = 0.0f;
#pragma unroll
        for (int nt = 0; nt < 8; ++nt) {
            float p0 = __expf(cS[nt][0] - mn0);
            float p1 = __expf(cS[nt][1] - mn0);
            float p2 = __expf(cS[nt][2] - mn1);
            float p3 = __expf(cS[nt][3] - mn1);
            float h0 = hr(p0), h1 = hr(p1), h2 = hr(p2), h3 = hr(p3);
            s0 += h0 + h1;
            s1 += h2 + h3;
            int ks = nt >> 1;
            int o = (nt & 1) * 2;
            ph[ks][o] = hpack(h0, h1);
            ph[ks][o + 1] = hpack(h2, h3);
        }
        s0 += __shfl_xor_sync(0xffffffffu, s0, 1);
        s0 += __shfl_xor_sync(0xffffffffu, s0, 2);
        s1 += __shfl_xor_sync(0xffffffffu, s1, 1);
        s1 += __shfl_xor_sync(0xffffffffu, s1, 2);
        l0 = l0 * a0 + s0;
        l1 = l1 * a1 + s1;

        // ---- O = O*alpha + Ph·Vh (single pass) ----
#pragma unroll
        for (int nt = 0; nt < 8; ++nt) {
            cO[nt][0] *= a0; cO[nt][1] *= a0;
            cO[nt][2] *= a1; cO[nt][3] *= a1;
        }
        uint32_t vBase = sb + (uint32_t)st * FST + FT +
                         (uint32_t)((lane & 15) * FPB + (lane >> 4) * 16);
#pragma unroll
        for (int ks = 0; ks < 4; ++ks) {
#pragma unroll
            for (int np = 0; np < 4; ++np) {
                uint32_t a = vBase + (uint32_t)(ks * 16 * FPB + np * 32);
                uint32_t vh4[4];
                ldx4t(vh4, a);
                mma_f16(cO[2 * np], ph[ks], vh4[0], vh4[1]);
                mma_f16(cO[2 * np + 1], ph[ks], vh4[2], vh4[3]);
            }
        }
    }
#undef STAGE_KV
#undef LOAD_TILE

    // ---- finalize: scale by 1/l, round to fp16 for the Wo GEMM ----
    float li0 = 1.0f / l0, li1 = 1.0f / l1;
    int b = bh >> 4, h = bh & 15;
    int row0 = qb + w * 16 + g;
    size_t base0 = ((size_t)(b * S + row0)) * D_MODEL + h * HEAD_DIM;
    size_t base1 = base0 + (size_t)8 * D_MODEL;
#pragma unroll
    for (int nt = 0; nt < 8; ++nt) {
        int d = nt * 8 + 2 * t;
        *(uint32_t*)(OH + base0 + d) =
            hpack(hr(cO[nt][0] * li0), hr(cO[nt][1] * li0));
        *(uint32_t*)(OH + base1 + d) =
            hpack(hr(cO[nt][2] * li1), hr(cO[nt][3] * li1));
    }
}

// ---------------- host side ----------------
extern "C" void kernel_launch(void* const* d_in, const int* in_sizes, int n_in,
                              void* d_out, int out_size) {
    const float* x  = (const float*)d_in[0];
    const float* Wq = (const float*)d_in[1];
    const float* Wk = (const float*)d_in[2];
    const float* Wv = (const float*)d_in[3];
    const float* Wo = (const float*)d_in[4];

    int B = in_sizes[0] / (SEQ * D_MODEL);
    if (B < 1) B = 1;
    if (B > MAXB) B = MAXB;
    int T = B * SEQ;
    int BH = B * N_HEADS;

    float *q, *k;
    ushort_t *qh, *ql, *kh, *vh, *xh, *wh;
    cudaGetSymbolAddress((void**)&q, g_q);
    cudaGetSymbolAddress((void**)&k, g_k);
    cudaGetSymbolAddress((void**)&qh, g_qh);
    cudaGetSymbolAddress((void**)&ql, g_ql);
    cudaGetSymbolAddress((void**)&kh, g_kh);
    cudaGetSymbolAddress((void**)&vh, g_vh);
    cudaGetSymbolAddress((void**)&xh, g_xh);
    cudaGetSymbolAddress((void**)&wh, g_wh);

    const int GSMEM = 2 * STAGEB;   // 40960
    cudaFuncSetAttribute(tc_gemm<1>, cudaFuncAttributeMaxDynamicSharedMemorySize, GSMEM);
    cudaFuncSetAttribute(tc_gemm<0>, cudaFuncAttributeMaxDynamicSharedMemorySize, GSMEM);
    cudaFuncSetAttribute(flash_f16, cudaFuncAttributeMaxDynamicSharedMemorySize, FL_SMEM);

    const size_t WSZ = (size_t)D_MODEL * D_MODEL;

    // 1) single fused split launch: x + all 4 weights (fp16 round)
    int xn4 = T * D_MODEL / 4;
    split_all<<<dim3(160, 5), 256>>>(x, Wq, Wk, Wv, Wo, (uint2*)xh, wh, xn4);

    // 2) QKV projections (1-pass fp16): q,k fp32; V written fp16
    tc_gemm<1><<<dim3(T / 128, D_MODEL / 128, 3), 256, GSMEM>>>(
        xh, wh, q, k, vh, SEQ);

    // 3) fused RoPE: Q split fp16 hi/lo (scaled), K rounded fp16
    int tot = BH * SEQ * 32;
    rope_split<<<(tot + 255) / 256, 256>>>(q, k, qh, ql, kh, BH, SEQ);

    // 4) flash attention (unchanged structure; writes rounded fp16 O)
    flash_f16<<<dim3(SEQ / 64, BH), 128, FL_SMEM>>>(qh, ql, kh, vh, xh, SEQ);

    // 5) output projection (1-pass fp16)
    tc_gemm<0><<<dim3(T / 128, D_MODEL / 128, 1), 256, GSMEM>>>(
        xh, wh + 3 * WSZ, (float*)d_out, nullptr, nullptr, SEQ);
}